// round 9
// baseline (speedup 1.0000x reference)
#include <cuda_runtime.h>
#include <cuda_bf16.h>
#include <cstdint>

// Hamming1Layer fused kernel, v7: asymmetric warp specialization + decoupled
// named-barrier pipeline.
// y[b,c,l] = (w_self*x[b,c,l] + sum_k w_bits[k]*x[b,c,l^(1<<k)]) / 15
// out[b,o,l] = sum_c mix_w[o,c]*y[b,c,l] + mix_b[o]
// B=32, C_IN=32, C_OUT=64, L=16384, N_BITS=14.
//
// v7 vs v6 (94.7us, L1-cyc + fma-cyc ~= wall -> phases still serialized):
//  - TPB=384: 4 producer warps (gather) + 8 consumer warps (mix GEMM)
//    -> consumer chunk time halves, 24 warps/SM (was 16)
//  - full/free named barriers (bar.arrive / bar.sync) per buffer parity:
//    producers run ahead instead of blocking on consumers each chunk
//  - consumer tile 4o x 4pair (32 acc regs) -> fits launch_bounds(384,2) cap

#define NBITS   14
#define LPOW    16384
#define CIN     32
#define COUT    64
#define TILE_L  512
#define CHUNK_L 128
#define NCHUNK  (TILE_L / CHUNK_L)     // 4
#define CQUADS  (CHUNK_L / 4)          // 32
#define CPAIRS  (CHUNK_L / 2)          // 64
#define TPB     384
#define NPROD   128                    // producer threads (4 warps)

// ---- smem map (bytes) ----
#define SMEM_XB    0                               // bf16 [CIN][TILE_L]        = 32 KiB
#define SMEM_YB    32768                           // f32  [2][CIN][CHUNK_L]    = 32 KiB
#define SMEM_W     65536                           // u64  [CIN][COUT] (w,w)    = 16 KiB
#define SMEM_B     81920                           // u64  [COUT] (b,b)         = 512 B
#define SMEM_TOTAL 82432                           // ~80.5 KiB -> 2 blocks/SM

// named barriers: 1+p = "chunk p%2 full", 3+p = "buffer p%2 free"
#define BAR_SYNC(id)   asm volatile("bar.sync %0, %1;"   :: "r"(id), "r"(TPB) : "memory")
#define BAR_ARRIVE(id) asm volatile("bar.arrive %0, %1;" :: "r"(id), "r"(TPB) : "memory")

__device__ __forceinline__ uint64_t pack2(float lo, float hi) {
    uint64_t r;
    asm("mov.b64 %0, {%1, %2};" : "=l"(r) : "f"(lo), "f"(hi));
    return r;
}
__device__ __forceinline__ void unpack2(uint64_t v, float& lo, float& hi) {
    asm("mov.b64 {%0, %1}, %2;" : "=f"(lo), "=f"(hi) : "l"(v));
}
__device__ __forceinline__ uint64_t fma2(uint64_t a, uint64_t b, uint64_t c) {
    uint64_t d;
    asm("fma.rn.f32x2 %0, %1, %2, %3;" : "=l"(d) : "l"(a), "l"(b), "l"(c));
    return d;
}
__device__ __forceinline__ uint64_t mul2(uint64_t a, uint64_t b) {
    uint64_t d;
    asm("mul.rn.f32x2 %0, %1, %2;" : "=l"(d) : "l"(a), "l"(b));
    return d;
}
__device__ __forceinline__ uint64_t add2(uint64_t a, uint64_t b) {
    uint64_t d;
    asm("add.rn.f32x2 %0, %1, %2;" : "=l"(d) : "l"(a), "l"(b));
    return d;
}
// bf16x2 word -> f32x2 pair (elem0 -> lo, elem1 -> hi)
__device__ __forceinline__ uint64_t bfp_to_f32x2(uint32_t v) {
    uint32_t lo = v << 16;
    uint32_t hi = v & 0xFFFF0000u;
    uint64_t r;
    asm("mov.b64 %0, {%1, %2};" : "=l"(r) : "r"(lo), "r"(hi));
    return r;
}
// two f32 -> bf16x2 word (a -> lo, b -> hi)
__device__ __forceinline__ uint32_t f2_to_bfp(float a, float b) {
    uint32_t r;
    asm("cvt.rn.bf16x2.f32 %0, %1, %2;" : "=r"(r) : "f"(b), "f"(a));
    return r;
}

extern __shared__ unsigned char smem_raw[];

__global__ __launch_bounds__(TPB, 2)
void hamming_kernel(const float* __restrict__ x,
                    const float* __restrict__ w_self,
                    const float* __restrict__ w_bits,
                    const float* __restrict__ mix_w,
                    const float* __restrict__ mix_b,
                    float* __restrict__ out)
{
    uint32_t*  sh_xb = (uint32_t*)(smem_raw + SMEM_XB);   // bf16x2 words [c][TILE_L/2]
    float*     sh_y  = (float*)   (smem_raw + SMEM_YB);   // [2][c][CHUNK_L]
    uint64_t*  sh_w  = (uint64_t*)(smem_raw + SMEM_W);
    uint64_t*  sh_b  = (uint64_t*)(smem_raw + SMEM_B);

    const int tid   = threadIdx.x;
    const int tile  = blockIdx.x;            // 0..31
    const int b     = blockIdx.y;            // 0..31
    const int lbase = tile * TILE_L;

    // ---- cooperative staging (all 384 threads) ----
    const float inv15 = 1.0f / 15.0f;
    for (int e = tid; e < CIN * COUT; e += TPB) {
        int o = e & 63, c = e >> 6;
        float w = mix_w[o * CIN + c] * inv15;
        sh_w[c * COUT + o] = pack2(w, w);
    }
    if (tid < COUT) {
        float v = mix_b[tid];
        sh_b[tid] = pack2(v, v);
    }

    const float4* xg4 = (const float4*)(x + (size_t)b * CIN * LPOW);
    for (int j = tid; j < CIN * TILE_L / 4; j += TPB) {     // 4096 float4 slots
        int c  = j >> 7;                 // 128 float4 per c
        int lw = j & 127;
        float4 f = xg4[(size_t)c * (LPOW / 4) + (lbase >> 2) + lw];
        uint2 p;
        p.x = f2_to_bfp(f.x, f.y);
        p.y = f2_to_bfp(f.z, f.w);
        *(uint2*)(sh_xb + c * (TILE_L / 2) + lw * 2) = p;
    }
    __syncthreads();

    if (tid < NPROD) {
        // ---------------- producer: 4 warps, gather chunks 0..3 ----------------
        const float ws = *w_self;
        const uint64_t ws2 = pack2(ws, ws);
        uint64_t wb2[NBITS];
        #pragma unroll
        for (int k = 0; k < NBITS; ++k) {
            float v = w_bits[k];
            wb2[k] = pack2(v, v);
        }
        const float* xb = x + (size_t)b * CIN * LPOW;

        for (int ck = 0; ck < NCHUNK; ++ck) {
            if (ck >= 2) BAR_SYNC(3 + (ck & 1));             // buffer free?
            float* ybuf = sh_y + (ck & 1) * CIN * CHUNK_L;

            #pragma unroll 2
            for (int it = 0; it < (CIN * CQUADS) / NPROD; ++it) {   // 8 iters
                int idx = it * NPROD + tid;
                int c   = idx >> 5;              // 0..31
                int ql  = idx & 31;              // quad in chunk
                int qg  = ck * CQUADS + ql;      // quad in tile [0,128)

                const float4*   xc4 = (const float4*)(xb + (size_t)c * LPOW);
                const uint32_t* row = sh_xb + c * (TILE_L / 2);

                // issue global loads (self f32 + 5 remote, L2-hot)
                float4 s   = xc4[(lbase >> 2) + qg];
                float4 g9  = xc4[((lbase ^ (1 <<  9)) >> 2) + qg];
                float4 g10 = xc4[((lbase ^ (1 << 10)) >> 2) + qg];
                float4 g11 = xc4[((lbase ^ (1 << 11)) >> 2) + qg];
                float4 g12 = xc4[((lbase ^ (1 << 12)) >> 2) + qg];
                float4 g13 = xc4[((lbase ^ (1 << 13)) >> 2) + qg];

                // chain A: self + bits 0,1 (register permutes)
                uint64_t s01 = pack2(s.x, s.y), s23 = pack2(s.z, s.w);
                uint64_t a01 = mul2(ws2, s01);
                uint64_t a23 = mul2(ws2, s23);
                a01 = fma2(wb2[0], pack2(s.y, s.x), a01);
                a23 = fma2(wb2[0], pack2(s.w, s.z), a23);
                a01 = fma2(wb2[1], s23, a01);
                a23 = fma2(wb2[1], s01, a23);

                // chain B: bits 2..8 from bf16 tile (independent chain)
                uint64_t b01, b23;
                {
                    uint2 n = *(const uint2*)(row + (qg ^ 1) * 2);
                    b01 = mul2(wb2[2], bfp_to_f32x2(n.x));
                    b23 = mul2(wb2[2], bfp_to_f32x2(n.y));
                }
                #pragma unroll
                for (int k = 3; k <= 8; ++k) {
                    int qn = qg ^ (1 << (k - 2));
                    uint2 n = *(const uint2*)(row + qn * 2);
                    b01 = fma2(wb2[k], bfp_to_f32x2(n.x), b01);
                    b23 = fma2(wb2[k], bfp_to_f32x2(n.y), b23);
                }

                // chain A: remote f32 quads
                a01 = fma2(wb2[ 9], pack2(g9.x,  g9.y),  a01);
                a23 = fma2(wb2[ 9], pack2(g9.z,  g9.w),  a23);
                a01 = fma2(wb2[10], pack2(g10.x, g10.y), a01);
                a23 = fma2(wb2[10], pack2(g10.z, g10.w), a23);
                a01 = fma2(wb2[11], pack2(g11.x, g11.y), a01);
                a23 = fma2(wb2[11], pack2(g11.z, g11.w), a23);
                a01 = fma2(wb2[12], pack2(g12.x, g12.y), a01);
                a23 = fma2(wb2[12], pack2(g12.z, g12.w), a23);
                a01 = fma2(wb2[13], pack2(g13.x, g13.y), a01);
                a23 = fma2(wb2[13], pack2(g13.z, g13.w), a23);

                a01 = add2(a01, b01);
                a23 = add2(a23, b23);

                float y0, y1, y2, y3;
                unpack2(a01, y0, y1);
                unpack2(a23, y2, y3);
                *(float4*)(ybuf + c * CHUNK_L + ql * 4) = make_float4(y0, y1, y2, y3);
            }
            BAR_ARRIVE(1 + (ck & 1));                        // chunk full
        }
    } else {
        // ---------------- consumer: 8 warps, mix chunks 0..3 ----------------
        const int tl = tid - NPROD;          // 0..255
        const int og = tl >> 4;              // 0..15 -> o rows [4og, 4og+4)
        const int pg = tl & 15;              // pairs pg + 16j
        const int ob = og * 4;
        uint64_t* outp = (uint64_t*)out + (size_t)b * COUT * (LPOW / 2) + (lbase >> 1);

        for (int ck = 0; ck < NCHUNK; ++ck) {
            BAR_SYNC(1 + (ck & 1));                          // chunk full?
            const uint64_t* ybuf = (const uint64_t*)(sh_y + (ck & 1) * CIN * CHUNK_L);

            uint64_t acc[4][4];
            #pragma unroll
            for (int i = 0; i < 4; ++i) {
                uint64_t bias = sh_b[ob + i];
                #pragma unroll
                for (int j = 0; j < 4; ++j) acc[i][j] = bias;
            }

            #pragma unroll 4
            for (int c = 0; c < CIN; ++c) {
                // w: 4 packed u64 = 2 LDS.128, broadcast within 16-lane group
                const ulonglong2* wr = (const ulonglong2*)(sh_w + c * COUT + ob);
                ulonglong2 wA = wr[0], wB = wr[1];

                // y: 4 pairs at stride 16 -> conflict-free, og-duplicated (merge)
                const uint64_t* yc = ybuf + c * CPAIRS + pg;
                uint64_t y0 = yc[0], y1 = yc[16], y2 = yc[32], y3 = yc[48];

                acc[0][0] = fma2(wA.x, y0, acc[0][0]); acc[0][1] = fma2(wA.x, y1, acc[0][1]);
                acc[0][2] = fma2(wA.x, y2, acc[0][2]); acc[0][3] = fma2(wA.x, y3, acc[0][3]);
                acc[1][0] = fma2(wA.y, y0, acc[1][0]); acc[1][1] = fma2(wA.y, y1, acc[1][1]);
                acc[1][2] = fma2(wA.y, y2, acc[1][2]); acc[1][3] = fma2(wA.y, y3, acc[1][3]);
                acc[2][0] = fma2(wB.x, y0, acc[2][0]); acc[2][1] = fma2(wB.x, y1, acc[2][1]);
                acc[2][2] = fma2(wB.x, y2, acc[2][2]); acc[2][3] = fma2(wB.x, y3, acc[2][3]);
                acc[3][0] = fma2(wB.y, y0, acc[3][0]); acc[3][1] = fma2(wB.y, y1, acc[3][1]);
                acc[3][2] = fma2(wB.y, y2, acc[3][2]); acc[3][3] = fma2(wB.y, y3, acc[3][3]);
            }
            BAR_ARRIVE(3 + (ck & 1));                        // buffer free

            uint64_t* ochunk = outp + ck * CPAIRS + pg;
            #pragma unroll
            for (int i = 0; i < 4; ++i) {
                uint64_t* orow = ochunk + (size_t)(ob + i) * (LPOW / 2);
                orow[0]  = acc[i][0];
                orow[16] = acc[i][1];
                orow[32] = acc[i][2];
                orow[48] = acc[i][3];
            }
        }
    }
}

extern "C" void kernel_launch(void* const* d_in, const int* in_sizes, int n_in,
                              void* d_out, int out_size)
{
    const float* x      = (const float*)d_in[0];
    const float* w_self = (const float*)d_in[1];
    const float* w_bits = (const float*)d_in[2];
    const float* mix_w  = (const float*)d_in[3];
    const float* mix_b  = (const float*)d_in[4];
    float* out = (float*)d_out;

    cudaFuncSetAttribute(hamming_kernel,
                         cudaFuncAttributeMaxDynamicSharedMemorySize, SMEM_TOTAL);

    dim3 grid(LPOW / TILE_L, 32, 1);   // (32 tiles, 32 batches) = 1024 blocks
    hamming_kernel<<<grid, TPB, SMEM_TOTAL>>>(x, w_self, w_bits, mix_w, mix_b, out);
}

// round 11
// speedup vs baseline: 1.4331x; 1.4331x over previous
#include <cuda_runtime.h>
#include <cuda_bf16.h>
#include <cstdint>

// Hamming1Layer fused kernel, v9: v8 with the B-fragment fix.
// y[b,c,l] = (w_self*x[b,c,l] + sum_k w_bits[k]*x[b,c,l^(1<<k)]) / 15
// out[b,o,l] = sum_c mix_w[o,c]*y[b,c,l] + mix_b[o]
// B=32, C_IN=32, C_OUT=64, L=16384, N_BITS=14.
//
// v9 vs v8 (WRONG results, rel_err 1.33):
//  - B (W) fragments must be loaded with NON-trans ldmatrix: for row.col mma,
//    b0 = B[k=2t][n=g] = W[o=g][c=2t] = non-trans fragment of row-major W.
//    v8 used .trans -> transposed garbage.
//  - W rows padded to 40 bf16 (80 B): 8 ldmatrix row addrs distinct mod 128
//    -> single-phase (stride 64 B was 4-way conflicted).
// Mix runs on tensor cores: D = Wh.Yh + Wh.Yl + Wl.Yh (bf16 split, fp32 accum).

#define NBITS   14
#define LPOW    16384
#define CIN     32
#define COUT    64
#define TILE_L  512
#define CHUNK_L 128
#define NCHUNK  (TILE_L / CHUNK_L)     // 4
#define CQUADS  (CHUNK_L / 4)          // 32
#define TPB     256
#define NPROD   128

// ---- smem map (bytes) ----
#define YROW    136                    // bf16 elems per y row (128 + 8 pad)
#define WROW    40                     // bf16 elems per W row (32 + 8 pad)
#define YSPLIT  (CIN * YROW * 2)       // one split plane = 8704 B
#define YBUF    (2 * YSPLIT)           // h + l planes = 17408 B
#define SMEM_XB    0                   // bf16 [CIN][TILE_L]          = 32768
#define SMEM_Y     32768               // [2 buf][h/l][CIN][YROW]     = 34816
#define SMEM_WH    67584               // bf16 [COUT][WROW]           = 5120
#define SMEM_WL    72704               // bf16 [COUT][WROW]           = 5120
#define SMEM_BIAS  77824               // f32 [COUT]                  = 256
#define SMEM_TOTAL 78080               // -> 2 blocks/SM

__device__ __forceinline__ uint64_t pack2(float lo, float hi) {
    uint64_t r;
    asm("mov.b64 %0, {%1, %2};" : "=l"(r) : "f"(lo), "f"(hi));
    return r;
}
__device__ __forceinline__ void unpack2(uint64_t v, float& lo, float& hi) {
    asm("mov.b64 {%0, %1}, %2;" : "=f"(lo), "=f"(hi) : "l"(v));
}
__device__ __forceinline__ uint64_t fma2(uint64_t a, uint64_t b, uint64_t c) {
    uint64_t d;
    asm("fma.rn.f32x2 %0, %1, %2, %3;" : "=l"(d) : "l"(a), "l"(b), "l"(c));
    return d;
}
__device__ __forceinline__ uint64_t mul2(uint64_t a, uint64_t b) {
    uint64_t d;
    asm("mul.rn.f32x2 %0, %1, %2;" : "=l"(d) : "l"(a), "l"(b));
    return d;
}
__device__ __forceinline__ uint64_t add2(uint64_t a, uint64_t b) {
    uint64_t d;
    asm("add.rn.f32x2 %0, %1, %2;" : "=l"(d) : "l"(a), "l"(b));
    return d;
}
__device__ __forceinline__ uint64_t sub2(uint64_t a, uint64_t b) {
    uint64_t d;
    asm("sub.rn.f32x2 %0, %1, %2;" : "=l"(d) : "l"(a), "l"(b));
    return d;
}
// bf16x2 word -> f32x2 pair (elem0 -> lo, elem1 -> hi)
__device__ __forceinline__ uint64_t bfp_to_f32x2(uint32_t v) {
    uint32_t lo = v << 16;
    uint32_t hi = v & 0xFFFF0000u;
    uint64_t r;
    asm("mov.b64 %0, {%1, %2};" : "=l"(r) : "r"(lo), "r"(hi));
    return r;
}
// two f32 -> bf16x2 word (a -> lo, b -> hi)
__device__ __forceinline__ uint32_t f2_to_bfp(float a, float b) {
    uint32_t r;
    asm("cvt.rn.bf16x2.f32 %0, %1, %2;" : "=r"(r) : "f"(b), "f"(a));
    return r;
}

#define LDSM_X4_T(d, addr)                                                      \
    asm volatile("ldmatrix.sync.aligned.m8n8.x4.trans.shared.b16 "              \
                 "{%0,%1,%2,%3}, [%4];"                                         \
                 : "=r"((d)[0]), "=r"((d)[1]), "=r"((d)[2]), "=r"((d)[3])       \
                 : "r"(addr))

// non-trans x2: B fragment from row-major W (b0 = W[o=g][c=2t])
#define LDSM_X2(d0, d1, addr)                                                   \
    asm volatile("ldmatrix.sync.aligned.m8n8.x2.shared.b16 "                    \
                 "{%0,%1}, [%2];"                                               \
                 : "=r"(d0), "=r"(d1) : "r"(addr))

#define MMA_BF16(c, a, b0, b1)                                                  \
    asm volatile("mma.sync.aligned.m16n8k16.row.col.f32.bf16.bf16.f32 "         \
                 "{%0,%1,%2,%3}, {%4,%5,%6,%7}, {%8,%9}, {%0,%1,%2,%3};"        \
                 : "+f"((c)[0]), "+f"((c)[1]), "+f"((c)[2]), "+f"((c)[3])       \
                 : "r"((a)[0]), "r"((a)[1]), "r"((a)[2]), "r"((a)[3]),          \
                   "r"(b0), "r"(b1))

extern __shared__ unsigned char smem_raw[];

__global__ __launch_bounds__(TPB, 2)
void hamming_kernel(const float* __restrict__ x,
                    const float* __restrict__ w_self,
                    const float* __restrict__ w_bits,
                    const float* __restrict__ mix_w,
                    const float* __restrict__ mix_b,
                    float* __restrict__ out)
{
    uint32_t*       sh_xb   = (uint32_t*)(smem_raw + SMEM_XB);
    __nv_bfloat16*  sh_wh   = (__nv_bfloat16*)(smem_raw + SMEM_WH);
    __nv_bfloat16*  sh_wl   = (__nv_bfloat16*)(smem_raw + SMEM_WL);
    float*          sh_bias = (float*)(smem_raw + SMEM_BIAS);
    const uint32_t  sbase   = (uint32_t)__cvta_generic_to_shared(smem_raw);

    const int tid   = threadIdx.x;
    const int wid   = tid >> 5;
    const int lane  = tid & 31;
    const int tile  = blockIdx.x;            // 0..31
    const int b     = blockIdx.y;            // 0..31
    const int lbase = tile * TILE_L;

    // ---- cooperative staging ----
    const float inv15 = 1.0f / 15.0f;
    for (int e = tid; e < CIN * COUT; e += TPB) {   // e = o*32 + c
        int o = e >> 5, c = e & 31;
        float w = mix_w[e] * inv15;
        __nv_bfloat16 wh = __float2bfloat16(w);
        sh_wh[o * WROW + c] = wh;
        sh_wl[o * WROW + c] = __float2bfloat16(w - __bfloat162float(wh));
    }
    if (tid < COUT) sh_bias[tid] = mix_b[tid];

    const float4* xg4 = (const float4*)(x + (size_t)b * CIN * LPOW);
    #pragma unroll
    for (int i = 0; i < (CIN * TILE_L / 4) / TPB; ++i) {    // 16 iters
        int j  = i * TPB + tid;
        int c  = j >> 7;
        int lw = j & 127;
        float4 f = xg4[(size_t)c * (LPOW / 4) + (lbase >> 2) + lw];
        uint2 p;
        p.x = f2_to_bfp(f.x, f.y);
        p.y = f2_to_bfp(f.z, f.w);
        *(uint2*)(sh_xb + c * (TILE_L / 2) + lw * 2) = p;
    }
    __syncthreads();

    if (tid < NPROD) {
        // ---------------- producer: 4 warps, gather chunks 0..3 ----------------
        const float ws = *w_self;
        const uint64_t ws2 = pack2(ws, ws);
        uint64_t wb2[NBITS];
        #pragma unroll
        for (int k = 0; k < NBITS; ++k) {
            float v = w_bits[k];
            wb2[k] = pack2(v, v);
        }
        const float* xb = x + (size_t)b * CIN * LPOW;

        for (int ck = 0; ck < NCHUNK; ++ck) {
            unsigned char* ybh = smem_raw + SMEM_Y + (ck & 1) * YBUF;
            unsigned char* ybl = ybh + YSPLIT;

            #pragma unroll 2
            for (int it = 0; it < (CIN * CQUADS) / NPROD; ++it) {   // 8 iters
                int idx = it * NPROD + tid;
                int c   = idx >> 5;              // 0..31
                int ql  = idx & 31;              // quad in chunk
                int qg  = ck * CQUADS + ql;      // quad in tile

                const float4*   xc4 = (const float4*)(xb + (size_t)c * LPOW);
                const uint32_t* row = sh_xb + c * (TILE_L / 2);

                float4 s   = xc4[(lbase >> 2) + qg];
                float4 g9  = xc4[((lbase ^ (1 <<  9)) >> 2) + qg];
                float4 g10 = xc4[((lbase ^ (1 << 10)) >> 2) + qg];
                float4 g11 = xc4[((lbase ^ (1 << 11)) >> 2) + qg];
                float4 g12 = xc4[((lbase ^ (1 << 12)) >> 2) + qg];
                float4 g13 = xc4[((lbase ^ (1 << 13)) >> 2) + qg];

                uint64_t s01 = pack2(s.x, s.y), s23 = pack2(s.z, s.w);
                uint64_t a01 = mul2(ws2, s01);
                uint64_t a23 = mul2(ws2, s23);
                a01 = fma2(wb2[0], pack2(s.y, s.x), a01);
                a23 = fma2(wb2[0], pack2(s.w, s.z), a23);
                a01 = fma2(wb2[1], s23, a01);
                a23 = fma2(wb2[1], s01, a23);

                uint64_t b01, b23;
                {
                    uint2 n = *(const uint2*)(row + (qg ^ 1) * 2);
                    b01 = mul2(wb2[2], bfp_to_f32x2(n.x));
                    b23 = mul2(wb2[2], bfp_to_f32x2(n.y));
                }
                #pragma unroll
                for (int k = 3; k <= 8; ++k) {
                    int qn = qg ^ (1 << (k - 2));
                    uint2 n = *(const uint2*)(row + qn * 2);
                    b01 = fma2(wb2[k], bfp_to_f32x2(n.x), b01);
                    b23 = fma2(wb2[k], bfp_to_f32x2(n.y), b23);
                }

                a01 = fma2(wb2[ 9], pack2(g9.x,  g9.y),  a01);
                a23 = fma2(wb2[ 9], pack2(g9.z,  g9.w),  a23);
                a01 = fma2(wb2[10], pack2(g10.x, g10.y), a01);
                a23 = fma2(wb2[10], pack2(g10.z, g10.w), a23);
                a01 = fma2(wb2[11], pack2(g11.x, g11.y), a01);
                a23 = fma2(wb2[11], pack2(g11.z, g11.w), a23);
                a01 = fma2(wb2[12], pack2(g12.x, g12.y), a01);
                a23 = fma2(wb2[12], pack2(g12.z, g12.w), a23);
                a01 = fma2(wb2[13], pack2(g13.x, g13.y), a01);
                a23 = fma2(wb2[13], pack2(g13.z, g13.w), a23);

                a01 = add2(a01, b01);
                a23 = add2(a23, b23);

                // split y -> bf16 hi/lo planes, layout [c][l] padded to YROW
                float y0, y1, y2, y3;
                unpack2(a01, y0, y1);
                unpack2(a23, y2, y3);
                uint32_t hA = f2_to_bfp(y0, y1);
                uint32_t hB = f2_to_bfp(y2, y3);
                uint64_t r01 = sub2(a01, bfp_to_f32x2(hA));
                uint64_t r23 = sub2(a23, bfp_to_f32x2(hB));
                float r0, r1, r2, r3;
                unpack2(r01, r0, r1);
                unpack2(r23, r2, r3);
                uint32_t lA = f2_to_bfp(r0, r1);
                uint32_t lB = f2_to_bfp(r2, r3);

                int yoff = c * (YROW * 2) + ql * 8;      // bytes
                *(uint2*)(ybh + yoff) = make_uint2(hA, hB);
                *(uint2*)(ybl + yoff) = make_uint2(lA, lB);
            }
            __syncthreads();    // chunk ck ready; consumer done with this buffer
        }
    } else {
        // ---------------- consumer: 4 warps, mma.sync mix ----------------
        const int wlocal = wid - 4;              // 0..3 -> l rows [32w, 32w+32)
        const int g = lane >> 2, t = lane & 3;
        const int wbase = wlocal * 32;

        // ldmatrix A (trans, from [c][l] memory = A^T):
        //   matrices: 0=(m0-7,k0-7) 1=(m8-15,k0-7) 2=(m0-7,k8-15) 3=(m8-15,k8-15)
        const int krow0 = (lane & 7) + ((lane >> 4) & 1) * 8;
        const int mcolA = ((lane >> 3) & 1) * 8;
        // ldmatrix B (non-trans, o-rows of W; lanes 0-15):
        //   matrix0 = (k0-7), matrix1 = (k8-15)
        const int brow = lane & 7;
        const int bk   = ((lane >> 3) & 1) * 8;
        const uint32_t whB = sbase + SMEM_WH;
        const uint32_t wlB = sbase + SMEM_WL;

        float* og = out + (size_t)b * COUT * LPOW;

        for (int ck = 0; ck < NCHUNK; ++ck) {
            __syncthreads();    // wait for producer chunk ck
            const uint32_t ybh = sbase + SMEM_Y + (ck & 1) * YBUF;
            const uint32_t ybl = ybh + YSPLIT;

            // A fragments: [mt][ks][4], hi and lo planes
            uint32_t Ah[2][2][4], Al[2][2][4];
            #pragma unroll
            for (int mt = 0; mt < 2; ++mt) {
                #pragma unroll
                for (int ks = 0; ks < 2; ++ks) {
                    uint32_t off = (uint32_t)(((ks * 16 + krow0) * YROW
                                   + wbase + mt * 16 + mcolA) * 2);
                    LDSM_X4_T(Ah[mt][ks], ybh + off);
                    LDSM_X4_T(Al[mt][ks], ybl + off);
                }
            }

            // accumulators init = bias (c0,c1 = o,o+1 at row g; c2,c3 row g+8)
            float acc[2][8][4];
            #pragma unroll
            for (int nt = 0; nt < 8; ++nt) {
                float2 bb = *(float2*)(sh_bias + nt * 8 + 2 * t);
                #pragma unroll
                for (int mt = 0; mt < 2; ++mt) {
                    acc[mt][nt][0] = bb.x; acc[mt][nt][1] = bb.y;
                    acc[mt][nt][2] = bb.x; acc[mt][nt][3] = bb.y;
                }
            }

            #pragma unroll
            for (int ks = 0; ks < 2; ++ks) {
                #pragma unroll
                for (int nt = 0; nt < 8; ++nt) {
                    uint32_t woff = (uint32_t)(((nt * 8 + brow) * WROW
                                    + ks * 16 + bk) * 2);
                    uint32_t bh0, bh1, bl0, bl1;
                    LDSM_X2(bh0, bh1, whB + woff);
                    MMA_BF16(acc[0][nt], Ah[0][ks], bh0, bh1);   // Wh.Yh
                    MMA_BF16(acc[1][nt], Ah[1][ks], bh0, bh1);
                    MMA_BF16(acc[0][nt], Al[0][ks], bh0, bh1);   // Wh.Yl
                    MMA_BF16(acc[1][nt], Al[1][ks], bh0, bh1);
                    LDSM_X2(bl0, bl1, wlB + woff);
                    MMA_BF16(acc[0][nt], Ah[0][ks], bl0, bl1);   // Wl.Yh
                    MMA_BF16(acc[1][nt], Ah[1][ks], bl0, bl1);
                }
            }

            // epilogue: D[m=l][n=o] -> out[b][o][l]; c2/c3 live at row m+8
            const int lch = lbase + ck * CHUNK_L + wbase;
            #pragma unroll
            for (int mt = 0; mt < 2; ++mt) {
                int l0 = lch + mt * 16 + g;
                #pragma unroll
                for (int nt = 0; nt < 8; ++nt) {
                    int o0 = nt * 8 + 2 * t;
                    og[(size_t)o0 * LPOW + l0]            = acc[mt][nt][0];
                    og[(size_t)(o0 + 1) * LPOW + l0]      = acc[mt][nt][1];
                    og[(size_t)o0 * LPOW + l0 + 8]        = acc[mt][nt][2];
                    og[(size_t)(o0 + 1) * LPOW + l0 + 8]  = acc[mt][nt][3];
                }
            }
        }
    }
}

extern "C" void kernel_launch(void* const* d_in, const int* in_sizes, int n_in,
                              void* d_out, int out_size)
{
    const float* x      = (const float*)d_in[0];
    const float* w_self = (const float*)d_in[1];
    const float* w_bits = (const float*)d_in[2];
    const float* mix_w  = (const float*)d_in[3];
    const float* mix_b  = (const float*)d_in[4];
    float* out = (float*)d_out;

    cudaFuncSetAttribute(hamming_kernel,
                         cudaFuncAttributeMaxDynamicSharedMemorySize, SMEM_TOTAL);

    dim3 grid(LPOW / TILE_L, 32, 1);   // (32 tiles, 32 batches) = 1024 blocks
    hamming_kernel<<<grid, TPB, SMEM_TOTAL>>>(x, w_self, w_bits, mix_w, mix_b, out);
}

// round 12
// speedup vs baseline: 1.6151x; 1.1270x over previous
#include <cuda_runtime.h>
#include <cuda_bf16.h>
#include <cstdint>

// Hamming1Layer fused kernel, v10: unified warps (no specialization) —
// all 8 warps gather each chunk, then all 8 warps run the HMMA mix.
// y[b,c,l] = (w_self*x[b,c,l] + sum_k w_bits[k]*x[b,c,l^(1<<k)]) / 15
// out[b,o,l] = sum_c mix_w[o,c]*y[b,c,l] + mix_b[o]
// B=32, C_IN=32, C_OUT=64, L=16384, N_BITS=14.
//
// v10 vs v9 (86.3us): producer-bound; 4 consumer warps idled (issue 25.6%).
// Mix on tensor cores is cheap enough that specialization wastes threads:
// gather now uses all 256 threads (2x throughput), mix uses all 8 warps
// (one m16 tile each). One __syncthreads per chunk, double-buffered y.
// Split MMA: D = Wh.Yh + Wh.Yl + Wl.Yh (bf16, fp32 accum).

#define NBITS   14
#define LPOW    16384
#define CIN     32
#define COUT    64
#define TILE_L  512
#define CHUNK_L 128
#define NCHUNK  (TILE_L / CHUNK_L)     // 4
#define CQUADS  (CHUNK_L / 4)          // 32
#define TPB     256

// ---- smem map (bytes) ----
#define YROW    136                    // bf16 elems per y row (128 + 8 pad; 272B stride -> distinct banks)
#define WROW    40                     // bf16 elems per W row (32 + 8 pad; 80B stride -> distinct banks)
#define YSPLIT  (CIN * YROW * 2)       // one split plane = 8704 B
#define YBUF    (2 * YSPLIT)           // h + l planes = 17408 B
#define SMEM_XB    0                   // bf16 [CIN][TILE_L]          = 32768
#define SMEM_Y     32768               // [2 buf][h/l][CIN][YROW]     = 34816
#define SMEM_WH    67584               // bf16 [COUT][WROW]           = 5120
#define SMEM_WL    72704               // bf16 [COUT][WROW]           = 5120
#define SMEM_BIAS  77824               // f32 [COUT]                  = 256
#define SMEM_TOTAL 78080               // -> 2 blocks/SM

__device__ __forceinline__ uint64_t pack2(float lo, float hi) {
    uint64_t r;
    asm("mov.b64 %0, {%1, %2};" : "=l"(r) : "f"(lo), "f"(hi));
    return r;
}
__device__ __forceinline__ void unpack2(uint64_t v, float& lo, float& hi) {
    asm("mov.b64 {%0, %1}, %2;" : "=f"(lo), "=f"(hi) : "l"(v));
}
__device__ __forceinline__ uint64_t fma2(uint64_t a, uint64_t b, uint64_t c) {
    uint64_t d;
    asm("fma.rn.f32x2 %0, %1, %2, %3;" : "=l"(d) : "l"(a), "l"(b), "l"(c));
    return d;
}
__device__ __forceinline__ uint64_t mul2(uint64_t a, uint64_t b) {
    uint64_t d;
    asm("mul.rn.f32x2 %0, %1, %2;" : "=l"(d) : "l"(a), "l"(b));
    return d;
}
__device__ __forceinline__ uint64_t add2(uint64_t a, uint64_t b) {
    uint64_t d;
    asm("add.rn.f32x2 %0, %1, %2;" : "=l"(d) : "l"(a), "l"(b));
    return d;
}
__device__ __forceinline__ uint64_t sub2(uint64_t a, uint64_t b) {
    uint64_t d;
    asm("sub.rn.f32x2 %0, %1, %2;" : "=l"(d) : "l"(a), "l"(b));
    return d;
}
// bf16x2 word -> f32x2 pair (elem0 -> lo, elem1 -> hi)
__device__ __forceinline__ uint64_t bfp_to_f32x2(uint32_t v) {
    uint32_t lo = v << 16;
    uint32_t hi = v & 0xFFFF0000u;
    uint64_t r;
    asm("mov.b64 %0, {%1, %2};" : "=l"(r) : "r"(lo), "r"(hi));
    return r;
}
// two f32 -> bf16x2 word (a -> lo, b -> hi)
__device__ __forceinline__ uint32_t f2_to_bfp(float a, float b) {
    uint32_t r;
    asm("cvt.rn.bf16x2.f32 %0, %1, %2;" : "=r"(r) : "f"(b), "f"(a));
    return r;
}

#define LDSM_X4_T(d, addr)                                                      \
    asm volatile("ldmatrix.sync.aligned.m8n8.x4.trans.shared.b16 "              \
                 "{%0,%1,%2,%3}, [%4];"                                         \
                 : "=r"((d)[0]), "=r"((d)[1]), "=r"((d)[2]), "=r"((d)[3])       \
                 : "r"(addr))

// non-trans x2: B fragment from row-major W (b0 = W[o=g][c=2t])
#define LDSM_X2(d0, d1, addr)                                                   \
    asm volatile("ldmatrix.sync.aligned.m8n8.x2.shared.b16 "                    \
                 "{%0,%1}, [%2];"                                               \
                 : "=r"(d0), "=r"(d1) : "r"(addr))

#define MMA_BF16(c, a, b0, b1)                                                  \
    asm volatile("mma.sync.aligned.m16n8k16.row.col.f32.bf16.bf16.f32 "         \
                 "{%0,%1,%2,%3}, {%4,%5,%6,%7}, {%8,%9}, {%0,%1,%2,%3};"        \
                 : "+f"((c)[0]), "+f"((c)[1]), "+f"((c)[2]), "+f"((c)[3])       \
                 : "r"((a)[0]), "r"((a)[1]), "r"((a)[2]), "r"((a)[3]),          \
                   "r"(b0), "r"(b1))

extern __shared__ unsigned char smem_raw[];

__global__ __launch_bounds__(TPB, 2)
void hamming_kernel(const float* __restrict__ x,
                    const float* __restrict__ w_self,
                    const float* __restrict__ w_bits,
                    const float* __restrict__ mix_w,
                    const float* __restrict__ mix_b,
                    float* __restrict__ out)
{
    uint32_t*       sh_xb   = (uint32_t*)(smem_raw + SMEM_XB);
    __nv_bfloat16*  sh_wh   = (__nv_bfloat16*)(smem_raw + SMEM_WH);
    __nv_bfloat16*  sh_wl   = (__nv_bfloat16*)(smem_raw + SMEM_WL);
    float*          sh_bias = (float*)(smem_raw + SMEM_BIAS);
    const uint32_t  sbase   = (uint32_t)__cvta_generic_to_shared(smem_raw);

    const int tid   = threadIdx.x;
    const int wid   = tid >> 5;
    const int lane  = tid & 31;
    const int tile  = blockIdx.x;            // 0..31
    const int b     = blockIdx.y;            // 0..31
    const int lbase = tile * TILE_L;

    // ---- cooperative staging ----
    const float inv15 = 1.0f / 15.0f;
    for (int e = tid; e < CIN * COUT; e += TPB) {   // e = o*32 + c
        int o = e >> 5, c = e & 31;
        float w = mix_w[e] * inv15;
        __nv_bfloat16 wh = __float2bfloat16(w);
        sh_wh[o * WROW + c] = wh;
        sh_wl[o * WROW + c] = __float2bfloat16(w - __bfloat162float(wh));
    }
    if (tid < COUT) sh_bias[tid] = mix_b[tid];

    const float4* xg4 = (const float4*)(x + (size_t)b * CIN * LPOW);
    #pragma unroll
    for (int i = 0; i < (CIN * TILE_L / 4) / TPB; ++i) {    // 16 iters
        int j  = i * TPB + tid;
        int c  = j >> 7;
        int lw = j & 127;
        float4 f = xg4[(size_t)c * (LPOW / 4) + (lbase >> 2) + lw];
        uint2 p;
        p.x = f2_to_bfp(f.x, f.y);
        p.y = f2_to_bfp(f.z, f.w);
        *(uint2*)(sh_xb + c * (TILE_L / 2) + lw * 2) = p;
    }

    // ---- per-thread gather weights ----
    const float ws = *w_self;
    const uint64_t ws2 = pack2(ws, ws);
    uint64_t wb2[NBITS];
    #pragma unroll
    for (int k = 0; k < NBITS; ++k) {
        float v = w_bits[k];
        wb2[k] = pack2(v, v);
    }

    // ---- mix-stage lane constants ----
    const int g = lane >> 2, t = lane & 3;
    const int wbase = wid * 16;              // warp's 16 l rows within chunk
    const int krow0 = (lane & 7) + ((lane >> 4) & 1) * 8;   // ldmatrix A (trans)
    const int mcolA = ((lane >> 3) & 1) * 8;
    const int brow  = lane & 7;                              // ldmatrix B (non-trans)
    const int bk    = ((lane >> 3) & 1) * 8;
    const uint32_t whB = sbase + SMEM_WH;
    const uint32_t wlB = sbase + SMEM_WL;

    const float* xb = x + (size_t)b * CIN * LPOW;
    float* og = out + (size_t)b * COUT * LPOW;

    __syncthreads();

    for (int ck = 0; ck < NCHUNK; ++ck) {
        // ================= gather (all 256 threads) =================
        unsigned char* ybh_w = smem_raw + SMEM_Y + (ck & 1) * YBUF;
        unsigned char* ybl_w = ybh_w + YSPLIT;

        #pragma unroll
        for (int it = 0; it < (CIN * CQUADS) / TPB; ++it) {   // 4 iters
            int idx = it * TPB + tid;
            int c   = idx >> 5;              // 0..31
            int ql  = idx & 31;              // quad in chunk
            int qg  = ck * CQUADS + ql;      // quad in tile

            const float4*   xc4 = (const float4*)(xb + (size_t)c * LPOW);
            const uint32_t* row = sh_xb + c * (TILE_L / 2);

            float4 s   = xc4[(lbase >> 2) + qg];
            float4 g9  = xc4[((lbase ^ (1 <<  9)) >> 2) + qg];
            float4 g10 = xc4[((lbase ^ (1 << 10)) >> 2) + qg];
            float4 g11 = xc4[((lbase ^ (1 << 11)) >> 2) + qg];
            float4 g12 = xc4[((lbase ^ (1 << 12)) >> 2) + qg];
            float4 g13 = xc4[((lbase ^ (1 << 13)) >> 2) + qg];

            uint64_t s01 = pack2(s.x, s.y), s23 = pack2(s.z, s.w);
            uint64_t a01 = mul2(ws2, s01);
            uint64_t a23 = mul2(ws2, s23);
            a01 = fma2(wb2[0], pack2(s.y, s.x), a01);
            a23 = fma2(wb2[0], pack2(s.w, s.z), a23);
            a01 = fma2(wb2[1], s23, a01);
            a23 = fma2(wb2[1], s01, a23);

            uint64_t b01, b23;
            {
                uint2 n = *(const uint2*)(row + (qg ^ 1) * 2);
                b01 = mul2(wb2[2], bfp_to_f32x2(n.x));
                b23 = mul2(wb2[2], bfp_to_f32x2(n.y));
            }
            #pragma unroll
            for (int k = 3; k <= 8; ++k) {
                int qn = qg ^ (1 << (k - 2));
                uint2 n = *(const uint2*)(row + qn * 2);
                b01 = fma2(wb2[k], bfp_to_f32x2(n.x), b01);
                b23 = fma2(wb2[k], bfp_to_f32x2(n.y), b23);
            }

            a01 = fma2(wb2[ 9], pack2(g9.x,  g9.y),  a01);
            a23 = fma2(wb2[ 9], pack2(g9.z,  g9.w),  a23);
            a01 = fma2(wb2[10], pack2(g10.x, g10.y), a01);
            a23 = fma2(wb2[10], pack2(g10.z, g10.w), a23);
            a01 = fma2(wb2[11], pack2(g11.x, g11.y), a01);
            a23 = fma2(wb2[11], pack2(g11.z, g11.w), a23);
            a01 = fma2(wb2[12], pack2(g12.x, g12.y), a01);
            a23 = fma2(wb2[12], pack2(g12.z, g12.w), a23);
            a01 = fma2(wb2[13], pack2(g13.x, g13.y), a01);
            a23 = fma2(wb2[13], pack2(g13.z, g13.w), a23);

            a01 = add2(a01, b01);
            a23 = add2(a23, b23);

            // split y -> bf16 hi/lo planes, layout [c][l] padded to YROW
            float y0, y1, y2, y3;
            unpack2(a01, y0, y1);
            unpack2(a23, y2, y3);
            uint32_t hA = f2_to_bfp(y0, y1);
            uint32_t hB = f2_to_bfp(y2, y3);
            uint64_t r01 = sub2(a01, bfp_to_f32x2(hA));
            uint64_t r23 = sub2(a23, bfp_to_f32x2(hB));
            float r0, r1, r2, r3;
            unpack2(r01, r0, r1);
            unpack2(r23, r2, r3);
            uint32_t lA = f2_to_bfp(r0, r1);
            uint32_t lB = f2_to_bfp(r2, r3);

            int yoff = c * (YROW * 2) + ql * 8;      // bytes
            *(uint2*)(ybh_w + yoff) = make_uint2(hA, hB);
            *(uint2*)(ybl_w + yoff) = make_uint2(lA, lB);
        }
        __syncthreads();    // chunk ck y ready (also: everyone done mixing ck-1)

        // ================= mix (all 8 warps, one m16 tile each) =================
        const uint32_t ybh = sbase + SMEM_Y + (ck & 1) * YBUF;
        const uint32_t ybl = ybh + YSPLIT;

        // A fragments: [ks][4], hi and lo planes, rows [wbase, wbase+16)
        uint32_t Ah[2][4], Al[2][4];
        #pragma unroll
        for (int ks = 0; ks < 2; ++ks) {
            uint32_t off = (uint32_t)(((ks * 16 + krow0) * YROW
                           + wbase + mcolA) * 2);
            LDSM_X4_T(Ah[ks], ybh + off);
            LDSM_X4_T(Al[ks], ybl + off);
        }

        // accumulators init = bias (c0,c1 = o,o+1 at row g; c2,c3 row g+8)
        float acc[8][4];
        #pragma unroll
        for (int nt = 0; nt < 8; ++nt) {
            float2 bb = *(float2*)(sh_bias + nt * 8 + 2 * t);
            acc[nt][0] = bb.x; acc[nt][1] = bb.y;
            acc[nt][2] = bb.x; acc[nt][3] = bb.y;
        }

        #pragma unroll
        for (int ks = 0; ks < 2; ++ks) {
            #pragma unroll
            for (int nt = 0; nt < 8; ++nt) {
                uint32_t woff = (uint32_t)(((nt * 8 + brow) * WROW
                                + ks * 16 + bk) * 2);
                uint32_t bh0, bh1, bl0, bl1;
                LDSM_X2(bh0, bh1, whB + woff);
                MMA_BF16(acc[nt], Ah[ks], bh0, bh1);   // Wh.Yh
                MMA_BF16(acc[nt], Al[ks], bh0, bh1);   // Wh.Yl
                LDSM_X2(bl0, bl1, wlB + woff);
                MMA_BF16(acc[nt], Ah[ks], bl0, bl1);   // Wl.Yh
            }
        }

        // epilogue: D[m=l][n=o] -> out[b][o][l]; c2/c3 live at row m+8
        const int l0 = lbase + ck * CHUNK_L + wbase + g;
        #pragma unroll
        for (int nt = 0; nt < 8; ++nt) {
            int o0 = nt * 8 + 2 * t;
            og[(size_t)o0 * LPOW + l0]            = acc[nt][0];
            og[(size_t)(o0 + 1) * LPOW + l0]      = acc[nt][1];
            og[(size_t)o0 * LPOW + l0 + 8]        = acc[nt][2];
            og[(size_t)(o0 + 1) * LPOW + l0 + 8]  = acc[nt][3];
        }
    }
}

extern "C" void kernel_launch(void* const* d_in, const int* in_sizes, int n_in,
                              void* d_out, int out_size)
{
    const float* x      = (const float*)d_in[0];
    const float* w_self = (const float*)d_in[1];
    const float* w_bits = (const float*)d_in[2];
    const float* mix_w  = (const float*)d_in[3];
    const float* mix_b  = (const float*)d_in[4];
    float* out = (float*)d_out;

    cudaFuncSetAttribute(hamming_kernel,
                         cudaFuncAttributeMaxDynamicSharedMemorySize, SMEM_TOTAL);

    dim3 grid(LPOW / TILE_L, 32, 1);   // (32 tiles, 32 batches) = 1024 blocks
    hamming_kernel<<<grid, TPB, SMEM_TOTAL>>>(x, w_self, w_bits, mix_w, mix_b, out);
}

// round 13
// speedup vs baseline: 1.6212x; 1.0038x over previous
#include <cuda_runtime.h>
#include <cuda_bf16.h>
#include <cstdint>

// Hamming1Layer fused kernel, v10: unified warps (no specialization) —
// all 8 warps gather each chunk, then all 8 warps run the HMMA mix.
// y[b,c,l] = (w_self*x[b,c,l] + sum_k w_bits[k]*x[b,c,l^(1<<k)]) / 15
// out[b,o,l] = sum_c mix_w[o,c]*y[b,c,l] + mix_b[o]
// B=32, C_IN=32, C_OUT=64, L=16384, N_BITS=14.
//
// v10 vs v9 (86.3us): producer-bound; 4 consumer warps idled (issue 25.6%).
// Mix on tensor cores is cheap enough that specialization wastes threads:
// gather now uses all 256 threads (2x throughput), mix uses all 8 warps
// (one m16 tile each). One __syncthreads per chunk, double-buffered y.
// Split MMA: D = Wh.Yh + Wh.Yl + Wl.Yh (bf16, fp32 accum).

#define NBITS   14
#define LPOW    16384
#define CIN     32
#define COUT    64
#define TILE_L  512
#define CHUNK_L 128
#define NCHUNK  (TILE_L / CHUNK_L)     // 4
#define CQUADS  (CHUNK_L / 4)          // 32
#define TPB     256

// ---- smem map (bytes) ----
#define YROW    136                    // bf16 elems per y row (128 + 8 pad; 272B stride -> distinct banks)
#define WROW    40                     // bf16 elems per W row (32 + 8 pad; 80B stride -> distinct banks)
#define YSPLIT  (CIN * YROW * 2)       // one split plane = 8704 B
#define YBUF    (2 * YSPLIT)           // h + l planes = 17408 B
#define SMEM_XB    0                   // bf16 [CIN][TILE_L]          = 32768
#define SMEM_Y     32768               // [2 buf][h/l][CIN][YROW]     = 34816
#define SMEM_WH    67584               // bf16 [COUT][WROW]           = 5120
#define SMEM_WL    72704               // bf16 [COUT][WROW]           = 5120
#define SMEM_BIAS  77824               // f32 [COUT]                  = 256
#define SMEM_TOTAL 78080               // -> 2 blocks/SM

__device__ __forceinline__ uint64_t pack2(float lo, float hi) {
    uint64_t r;
    asm("mov.b64 %0, {%1, %2};" : "=l"(r) : "f"(lo), "f"(hi));
    return r;
}
__device__ __forceinline__ void unpack2(uint64_t v, float& lo, float& hi) {
    asm("mov.b64 {%0, %1}, %2;" : "=f"(lo), "=f"(hi) : "l"(v));
}
__device__ __forceinline__ uint64_t fma2(uint64_t a, uint64_t b, uint64_t c) {
    uint64_t d;
    asm("fma.rn.f32x2 %0, %1, %2, %3;" : "=l"(d) : "l"(a), "l"(b), "l"(c));
    return d;
}
__device__ __forceinline__ uint64_t mul2(uint64_t a, uint64_t b) {
    uint64_t d;
    asm("mul.rn.f32x2 %0, %1, %2;" : "=l"(d) : "l"(a), "l"(b));
    return d;
}
__device__ __forceinline__ uint64_t add2(uint64_t a, uint64_t b) {
    uint64_t d;
    asm("add.rn.f32x2 %0, %1, %2;" : "=l"(d) : "l"(a), "l"(b));
    return d;
}
__device__ __forceinline__ uint64_t sub2(uint64_t a, uint64_t b) {
    uint64_t d;
    asm("sub.rn.f32x2 %0, %1, %2;" : "=l"(d) : "l"(a), "l"(b));
    return d;
}
// bf16x2 word -> f32x2 pair (elem0 -> lo, elem1 -> hi)
__device__ __forceinline__ uint64_t bfp_to_f32x2(uint32_t v) {
    uint32_t lo = v << 16;
    uint32_t hi = v & 0xFFFF0000u;
    uint64_t r;
    asm("mov.b64 %0, {%1, %2};" : "=l"(r) : "r"(lo), "r"(hi));
    return r;
}
// two f32 -> bf16x2 word (a -> lo, b -> hi)
__device__ __forceinline__ uint32_t f2_to_bfp(float a, float b) {
    uint32_t r;
    asm("cvt.rn.bf16x2.f32 %0, %1, %2;" : "=r"(r) : "f"(b), "f"(a));
    return r;
}

#define LDSM_X4_T(d, addr)                                                      \
    asm volatile("ldmatrix.sync.aligned.m8n8.x4.trans.shared.b16 "              \
                 "{%0,%1,%2,%3}, [%4];"                                         \
                 : "=r"((d)[0]), "=r"((d)[1]), "=r"((d)[2]), "=r"((d)[3])       \
                 : "r"(addr))

// non-trans x2: B fragment from row-major W (b0 = W[o=g][c=2t])
#define LDSM_X2(d0, d1, addr)                                                   \
    asm volatile("ldmatrix.sync.aligned.m8n8.x2.shared.b16 "                    \
                 "{%0,%1}, [%2];"                                               \
                 : "=r"(d0), "=r"(d1) : "r"(addr))

#define MMA_BF16(c, a, b0, b1)                                                  \
    asm volatile("mma.sync.aligned.m16n8k16.row.col.f32.bf16.bf16.f32 "         \
                 "{%0,%1,%2,%3}, {%4,%5,%6,%7}, {%8,%9}, {%0,%1,%2,%3};"        \
                 : "+f"((c)[0]), "+f"((c)[1]), "+f"((c)[2]), "+f"((c)[3])       \
                 : "r"((a)[0]), "r"((a)[1]), "r"((a)[2]), "r"((a)[3]),          \
                   "r"(b0), "r"(b1))

extern __shared__ unsigned char smem_raw[];

__global__ __launch_bounds__(TPB, 2)
void hamming_kernel(const float* __restrict__ x,
                    const float* __restrict__ w_self,
                    const float* __restrict__ w_bits,
                    const float* __restrict__ mix_w,
                    const float* __restrict__ mix_b,
                    float* __restrict__ out)
{
    uint32_t*       sh_xb   = (uint32_t*)(smem_raw + SMEM_XB);
    __nv_bfloat16*  sh_wh   = (__nv_bfloat16*)(smem_raw + SMEM_WH);
    __nv_bfloat16*  sh_wl   = (__nv_bfloat16*)(smem_raw + SMEM_WL);
    float*          sh_bias = (float*)(smem_raw + SMEM_BIAS);
    const uint32_t  sbase   = (uint32_t)__cvta_generic_to_shared(smem_raw);

    const int tid   = threadIdx.x;
    const int wid   = tid >> 5;
    const int lane  = tid & 31;
    const int tile  = blockIdx.x;            // 0..31
    const int b     = blockIdx.y;            // 0..31
    const int lbase = tile * TILE_L;

    // ---- cooperative staging ----
    const float inv15 = 1.0f / 15.0f;
    for (int e = tid; e < CIN * COUT; e += TPB) {   // e = o*32 + c
        int o = e >> 5, c = e & 31;
        float w = mix_w[e] * inv15;
        __nv_bfloat16 wh = __float2bfloat16(w);
        sh_wh[o * WROW + c] = wh;
        sh_wl[o * WROW + c] = __float2bfloat16(w - __bfloat162float(wh));
    }
    if (tid < COUT) sh_bias[tid] = mix_b[tid];

    const float4* xg4 = (const float4*)(x + (size_t)b * CIN * LPOW);
    #pragma unroll
    for (int i = 0; i < (CIN * TILE_L / 4) / TPB; ++i) {    // 16 iters
        int j  = i * TPB + tid;
        int c  = j >> 7;
        int lw = j & 127;
        float4 f = xg4[(size_t)c * (LPOW / 4) + (lbase >> 2) + lw];
        uint2 p;
        p.x = f2_to_bfp(f.x, f.y);
        p.y = f2_to_bfp(f.z, f.w);
        *(uint2*)(sh_xb + c * (TILE_L / 2) + lw * 2) = p;
    }

    // ---- per-thread gather weights ----
    const float ws = *w_self;
    const uint64_t ws2 = pack2(ws, ws);
    uint64_t wb2[NBITS];
    #pragma unroll
    for (int k = 0; k < NBITS; ++k) {
        float v = w_bits[k];
        wb2[k] = pack2(v, v);
    }

    // ---- mix-stage lane constants ----
    const int g = lane >> 2, t = lane & 3;
    const int wbase = wid * 16;              // warp's 16 l rows within chunk
    const int krow0 = (lane & 7) + ((lane >> 4) & 1) * 8;   // ldmatrix A (trans)
    const int mcolA = ((lane >> 3) & 1) * 8;
    const int brow  = lane & 7;                              // ldmatrix B (non-trans)
    const int bk    = ((lane >> 3) & 1) * 8;
    const uint32_t whB = sbase + SMEM_WH;
    const uint32_t wlB = sbase + SMEM_WL;

    const float* xb = x + (size_t)b * CIN * LPOW;
    float* og = out + (size_t)b * COUT * LPOW;

    __syncthreads();

    for (int ck = 0; ck < NCHUNK; ++ck) {
        // ================= gather (all 256 threads) =================
        unsigned char* ybh_w = smem_raw + SMEM_Y + (ck & 1) * YBUF;
        unsigned char* ybl_w = ybh_w + YSPLIT;

        #pragma unroll
        for (int it = 0; it < (CIN * CQUADS) / TPB; ++it) {   // 4 iters
            int idx = it * TPB + tid;
            int c   = idx >> 5;              // 0..31
            int ql  = idx & 31;              // quad in chunk
            int qg  = ck * CQUADS + ql;      // quad in tile

            const float4*   xc4 = (const float4*)(xb + (size_t)c * LPOW);
            const uint32_t* row = sh_xb + c * (TILE_L / 2);

            float4 s   = xc4[(lbase >> 2) + qg];
            float4 g9  = xc4[((lbase ^ (1 <<  9)) >> 2) + qg];
            float4 g10 = xc4[((lbase ^ (1 << 10)) >> 2) + qg];
            float4 g11 = xc4[((lbase ^ (1 << 11)) >> 2) + qg];
            float4 g12 = xc4[((lbase ^ (1 << 12)) >> 2) + qg];
            float4 g13 = xc4[((lbase ^ (1 << 13)) >> 2) + qg];

            uint64_t s01 = pack2(s.x, s.y), s23 = pack2(s.z, s.w);
            uint64_t a01 = mul2(ws2, s01);
            uint64_t a23 = mul2(ws2, s23);
            a01 = fma2(wb2[0], pack2(s.y, s.x), a01);
            a23 = fma2(wb2[0], pack2(s.w, s.z), a23);
            a01 = fma2(wb2[1], s23, a01);
            a23 = fma2(wb2[1], s01, a23);

            uint64_t b01, b23;
            {
                uint2 n = *(const uint2*)(row + (qg ^ 1) * 2);
                b01 = mul2(wb2[2], bfp_to_f32x2(n.x));
                b23 = mul2(wb2[2], bfp_to_f32x2(n.y));
            }
            #pragma unroll
            for (int k = 3; k <= 8; ++k) {
                int qn = qg ^ (1 << (k - 2));
                uint2 n = *(const uint2*)(row + qn * 2);
                b01 = fma2(wb2[k], bfp_to_f32x2(n.x), b01);
                b23 = fma2(wb2[k], bfp_to_f32x2(n.y), b23);
            }

            a01 = fma2(wb2[ 9], pack2(g9.x,  g9.y),  a01);
            a23 = fma2(wb2[ 9], pack2(g9.z,  g9.w),  a23);
            a01 = fma2(wb2[10], pack2(g10.x, g10.y), a01);
            a23 = fma2(wb2[10], pack2(g10.z, g10.w), a23);
            a01 = fma2(wb2[11], pack2(g11.x, g11.y), a01);
            a23 = fma2(wb2[11], pack2(g11.z, g11.w), a23);
            a01 = fma2(wb2[12], pack2(g12.x, g12.y), a01);
            a23 = fma2(wb2[12], pack2(g12.z, g12.w), a23);
            a01 = fma2(wb2[13], pack2(g13.x, g13.y), a01);
            a23 = fma2(wb2[13], pack2(g13.z, g13.w), a23);

            a01 = add2(a01, b01);
            a23 = add2(a23, b23);

            // split y -> bf16 hi/lo planes, layout [c][l] padded to YROW
            float y0, y1, y2, y3;
            unpack2(a01, y0, y1);
            unpack2(a23, y2, y3);
            uint32_t hA = f2_to_bfp(y0, y1);
            uint32_t hB = f2_to_bfp(y2, y3);
            uint64_t r01 = sub2(a01, bfp_to_f32x2(hA));
            uint64_t r23 = sub2(a23, bfp_to_f32x2(hB));
            float r0, r1, r2, r3;
            unpack2(r01, r0, r1);
            unpack2(r23, r2, r3);
            uint32_t lA = f2_to_bfp(r0, r1);
            uint32_t lB = f2_to_bfp(r2, r3);

            int yoff = c * (YROW * 2) + ql * 8;      // bytes
            *(uint2*)(ybh_w + yoff) = make_uint2(hA, hB);
            *(uint2*)(ybl_w + yoff) = make_uint2(lA, lB);
        }
        __syncthreads();    // chunk ck y ready (also: everyone done mixing ck-1)

        // ================= mix (all 8 warps, one m16 tile each) =================
        const uint32_t ybh = sbase + SMEM_Y + (ck & 1) * YBUF;
        const uint32_t ybl = ybh + YSPLIT;

        // A fragments: [ks][4], hi and lo planes, rows [wbase, wbase+16)
        uint32_t Ah[2][4], Al[2][4];
        #pragma unroll
        for (int ks = 0; ks < 2; ++ks) {
            uint32_t off = (uint32_t)(((ks * 16 + krow0) * YROW
                           + wbase + mcolA) * 2);
            LDSM_X4_T(Ah[ks], ybh + off);
            LDSM_X4_T(Al[ks], ybl + off);
        }

        // accumulators init = bias (c0,c1 = o,o+1 at row g; c2,c3 row g+8)
        float acc[8][4];
        #pragma unroll
        for (int nt = 0; nt < 8; ++nt) {
            float2 bb = *(float2*)(sh_bias + nt * 8 + 2 * t);
            acc[nt][0] = bb.x; acc[nt][1] = bb.y;
            acc[nt][2] = bb.x; acc[nt][3] = bb.y;
        }

        #pragma unroll
        for (int ks = 0; ks < 2; ++ks) {
            #pragma unroll
            for (int nt = 0; nt < 8; ++nt) {
                uint32_t woff = (uint32_t)(((nt * 8 + brow) * WROW
                                + ks * 16 + bk) * 2);
                uint32_t bh0, bh1, bl0, bl1;
                LDSM_X2(bh0, bh1, whB + woff);
                MMA_BF16(acc[nt], Ah[ks], bh0, bh1);   // Wh.Yh
                MMA_BF16(acc[nt], Al[ks], bh0, bh1);   // Wh.Yl
                LDSM_X2(bl0, bl1, wlB + woff);
                MMA_BF16(acc[nt], Ah[ks], bl0, bl1);   // Wl.Yh
            }
        }

        // epilogue: D[m=l][n=o] -> out[b][o][l]; c2/c3 live at row m+8
        const int l0 = lbase + ck * CHUNK_L + wbase + g;
        #pragma unroll
        for (int nt = 0; nt < 8; ++nt) {
            int o0 = nt * 8 + 2 * t;
            og[(size_t)o0 * LPOW + l0]            = acc[nt][0];
            og[(size_t)(o0 + 1) * LPOW + l0]      = acc[nt][1];
            og[(size_t)o0 * LPOW + l0 + 8]        = acc[nt][2];
            og[(size_t)(o0 + 1) * LPOW + l0 + 8]  = acc[nt][3];
        }
    }
}

extern "C" void kernel_launch(void* const* d_in, const int* in_sizes, int n_in,
                              void* d_out, int out_size)
{
    const float* x      = (const float*)d_in[0];
    const float* w_self = (const float*)d_in[1];
    const float* w_bits = (const float*)d_in[2];
    const float* mix_w  = (const float*)d_in[3];
    const float* mix_b  = (const float*)d_in[4];
    float* out = (float*)d_out;

    cudaFuncSetAttribute(hamming_kernel,
                         cudaFuncAttributeMaxDynamicSharedMemorySize, SMEM_TOTAL);

    dim3 grid(LPOW / TILE_L, 32, 1);   // (32 tiles, 32 batches) = 1024 blocks
    hamming_kernel<<<grid, TPB, SMEM_TOTAL>>>(x, w_self, w_bits, mix_w, mix_b, out);
}